// round 14
// baseline (speedup 1.0000x reference)
#include <cuda_runtime.h>
#include <cstdint>

// EfficientByteMUL — single persistent-wave kernel, register double-buffered.
// Layout: MARK_AX=0, OP_MUL=1, ALU_LO=16, ALU_HI=32, AX_CARRY_LO=48, AX_CARRY_HI=64,
// OUTPUT_LO=80, OUTPUT_HI=96, BD_DIM=128. GE pos-0 input is 3-sparse:
//   h_j = relu(a*W1[0,j] + b*W1[1,j] + W1[29,j] + b1[j]),  y = sum_j h_j*W2[j,40] + b2[40]
// Coeffs packed per block in smem: s_coeff[j] = (W1[0,j], W1[1,j], W1[29,j]+b1[j], W2[j,40]).

#define NUM_CTAS 512   // <= 592 resident at 4 CTAs/SM -> whole grid in one wave

__device__ __forceinline__ float comp_of(float4 v, int c) {
    return c == 0 ? v.x : (c == 1 ? v.y : (c == 2 ? v.z : v.w));
}

// Patch one active token. v = this lane's float4 of the token (elems 4*lane..4*lane+3).
__device__ __forceinline__ void patch_token(float4 v, float* __restrict__ otok,
                                            const float4* s_coeff, float b2v,
                                            int lane, unsigned FULL)
{
    // argmax over four 16-elem segments: [16,32)->lanes4..7, [32,48)->8..11,
    // [48,64)->12..15, [64,80)->16..19 (first-max wins: strict >, tie -> lower idx)
    float best = v.x; int bidx = 0;
    if (v.y > best) { best = v.y; bidx = 1; }
    if (v.z > best) { best = v.z; bidx = 2; }
    if (v.w > best) { best = v.w; bidx = 3; }
    int gidx = ((lane & 3) << 2) | bidx;

    #pragma unroll
    for (int off = 1; off <= 2; off <<= 1) {
        float ob = __shfl_xor_sync(FULL, best, off);
        int   oi = __shfl_xor_sync(FULL, gidx, off);
        if (ob > best || (ob == best && oi < gidx)) { best = ob; gidx = oi; }
    }

    int a_lo = __shfl_sync(FULL, gidx, 4);
    int a_hi = __shfl_sync(FULL, gidx, 8);
    int b_lo = __shfl_sync(FULL, gidx, 12);
    int b_hi = __shfl_sync(FULL, gidx, 16);

    float fa = (float)(a_lo | (a_hi << 4));
    float fb = (float)(b_lo | (b_hi << 4));

    // MLP: j = lane + 32*i, conflict-free LDS.128 from 4 KB smem table
    float acc = 0.0f;
    #pragma unroll
    for (int i = 0; i < 8; i++) {
        float4 c = s_coeff[lane + 32 * i];
        float h = fmaf(fa, c.x, fmaf(fb, c.y, c.z));
        h = fmaxf(h, 0.0f);
        acc = fmaf(h, c.w, acc);
    }
    #pragma unroll
    for (int off = 16; off; off >>= 1)
        acc += __shfl_xor_sync(FULL, acc, off);
    acc += b2v;

    int res = ((int)rintf(acc)) & 255;   // rintf == round-half-even == jnp.round
    int e_lo = 80 + (res & 15);          // owner lanes 20..23
    int e_hi = 96 + (res >> 4);          // owner lanes 24..27

    // Owner lane overwrites its element: lands after its own earlier STG.128.
    if ((e_lo >> 2) == lane) otok[e_lo] = comp_of(v, e_lo & 3) + 2.0f;
    if ((e_hi >> 2) == lane) otok[e_hi] = comp_of(v, e_hi & 3) + 2.0f;
}

__global__ void __launch_bounds__(256, 4)
byte_mul_kernel(const float* __restrict__ x,
                float* __restrict__ out,
                const float* __restrict__ W1,
                const float* __restrict__ b1,
                const float* __restrict__ W2,
                const float* __restrict__ b2,
                int n_tokens)
{
    __shared__ __align__(16) float4 s_coeff[256];
    __shared__ float s_b2;

    const unsigned FULL = 0xffffffffu;
    int tid  = threadIdx.x;
    int warp = tid >> 5;
    int lane = tid & 31;

    int gw = blockIdx.x * 8 + warp;      // global warp id
    int NW = gridDim.x * 8;              // total warps (4096)
    int ngroups = n_tokens >> 2;         // groups of 4 tokens

    // Prologue loads for first group (independent of smem — overlap coeff build)
    int g = gw;
    bool have = g < ngroups;
    float4 A0, A1, A2, A3;
    if (have) {
        const float4* xg = reinterpret_cast<const float4*>(x) + (size_t)g * 128;
        A0 = __ldcs(&xg[lane]);
        A1 = __ldcs(&xg[32 + lane]);
        A2 = __ldcs(&xg[64 + lane]);
        A3 = __ldcs(&xg[96 + lane]);
    }

    // Build coefficient table (256 threads, one entry each)
    s_coeff[tid] = make_float4(W1[tid], W1[256 + tid],
                               W1[29 * 256 + tid] + b1[tid], W2[tid * 64 + 40]);
    if (tid == 0) s_b2 = b2[40];
    __syncthreads();
    float b2v = s_b2;

    while (have) {
        // Issue next group's loads before touching A (keeps ~2KB/warp in flight)
        int gn = g + NW;
        bool haveN = gn < ngroups;
        float4 B0, B1, B2, B3;
        if (haveN) {
            const float4* xn = reinterpret_cast<const float4*>(x) + (size_t)gn * 128;
            B0 = __ldcs(&xn[lane]);
            B1 = __ldcs(&xn[32 + lane]);
            B2 = __ldcs(&xn[64 + lane]);
            B3 = __ldcs(&xn[96 + lane]);
        }

        // Active mask: lane 0 holds elems 0..3 of each token -> one broadcast
        int act = 0;
        if (lane == 0) {
            if (A0.x >= 0.5f && A0.y >= 0.5f) act |= 1;
            if (A1.x >= 0.5f && A1.y >= 0.5f) act |= 2;
            if (A2.x >= 0.5f && A2.y >= 0.5f) act |= 4;
            if (A3.x >= 0.5f && A3.y >= 0.5f) act |= 8;
        }
        act = __shfl_sync(FULL, act, 0);

        // Unconditional copy (each store depends only on its own load)
        float4* og = reinterpret_cast<float4*>(out) + (size_t)g * 128;
        __stcs(&og[      lane], A0);
        __stcs(&og[32  + lane], A1);
        __stcs(&og[64  + lane], A2);
        __stcs(&og[96  + lane], A3);

        // Patch active tokens from live registers
        if (act) {
            float* ob = out + (size_t)g * 512;
            if (act & 1) patch_token(A0, ob,       s_coeff, b2v, lane, FULL);
            if (act & 2) patch_token(A1, ob + 128, s_coeff, b2v, lane, FULL);
            if (act & 4) patch_token(A2, ob + 256, s_coeff, b2v, lane, FULL);
            if (act & 8) patch_token(A3, ob + 384, s_coeff, b2v, lane, FULL);
        }

        // Rotate
        A0 = B0; A1 = B1; A2 = B2; A3 = B3;
        g = gn; have = haveN;
    }

    // Ragged tail (n_tokens % 4 != 0; never taken for 65536): warp 0 of block 0
    int rem0 = ngroups << 2;
    if (blockIdx.x == 0 && warp == 0 && rem0 < n_tokens) {
        for (int t = rem0; t < n_tokens; t++) {
            const float4* xt = reinterpret_cast<const float4*>(x + (size_t)t * 128);
            float4*       ot = reinterpret_cast<float4*>(out + (size_t)t * 128);
            float4 v = xt[lane];
            int a = 0;
            if (lane == 0 && v.x >= 0.5f && v.y >= 0.5f) a = 1;
            a = __shfl_sync(FULL, a, 0);
            ot[lane] = v;
            if (a) patch_token(v, out + (size_t)t * 128, s_coeff, b2v, lane, FULL);
        }
    }
}

extern "C" void kernel_launch(void* const* d_in, const int* in_sizes, int n_in,
                              void* d_out, int out_size)
{
    const float* x  = (const float*)d_in[0];  // [8, 8192, 128]
    const float* W1 = (const float*)d_in[1];  // [64, 256]
    const float* b1 = (const float*)d_in[2];  // [256]
    const float* W2 = (const float*)d_in[3];  // [256, 64]
    const float* b2 = (const float*)d_in[4];  // [64]
    float* out = (float*)d_out;

    int n_tokens = in_sizes[0] / 128;         // 65536

    byte_mul_kernel<<<NUM_CTAS, 256>>>(x, out, W1, b1, W2, b2, n_tokens);
}